// round 5
// baseline (speedup 1.0000x reference)
#include <cuda_runtime.h>
#include <cuda_bf16.h>
#include <cstdint>
#include <math.h>

// Problem constants
#define B_      8192
#define ZD_     256
#define CD_     256
#define NSTEPS  32
#define H_      512
#define SZ      (B_*ZD_)      // 2097152
#define SZH     (B_*H_)       // 4194304
#define DT_     0.03125f
#define SQRTDT_ 0.17677669529663687f

// ---------------- device scratch ------------------------------------------------
__device__ float g_C  [SZH];                    // ctx@W1_ctx + b1 (fp32)
__device__ float g_z  [SZ];                     // z_prev (fp32)
__device__ float g_zn [SZ];                     // z_next (fp32)
__device__ float g_lw [SZ];                     // per-element log_w
__device__ double g_part[2048];

// bf16-split operand buffers
__device__ __nv_bfloat16 g_zb_hi[SZ],  g_zb_lo[SZ];     // current z for layer-1
__device__ __nv_bfloat16 g_ctxb_hi[SZ], g_ctxb_lo[SZ];  // ctx split
__device__ __nv_bfloat16 g_hf_hi[SZH], g_hf_lo[SZH];    // tanh fwd activations
__device__ __nv_bfloat16 g_hb_hi[SZH], g_hb_lo[SZH];    // tanh bwd activations
// transposed + split weights: [N, K] row-major
__device__ __nv_bfloat16 g_w1zt_hi[H_*ZD_], g_w1zt_lo[H_*ZD_];  // [512,256]
__device__ __nv_bfloat16 g_w1ct_hi[H_*CD_], g_w1ct_lo[H_*CD_];  // [512,256]
__device__ __nv_bfloat16 g_w2t_hi[ZD_*H_],  g_w2t_lo[ZD_*H_];   // [256,512]

// ---------------- helpers -------------------------------------------------------
__device__ __forceinline__ uint32_t smem_u32(const void* p) {
    uint32_t a;
    asm("{ .reg .u64 t; cvta.to.shared.u64 t, %1; cvt.u32.u64 %0, t; }" : "=r"(a) : "l"(p));
    return a;
}
__device__ __forceinline__ void cpa16(uint32_t s, const void* g) {
    asm volatile("cp.async.cg.shared.global [%0], [%1], 16;" :: "r"(s), "l"(g));
}
#define CPA_COMMIT() asm volatile("cp.async.commit_group;" ::: "memory")
#define CPA_WAIT1()  asm volatile("cp.async.wait_group 1;" ::: "memory")
#define CPA_WAIT0()  asm volatile("cp.async.wait_group 0;" ::: "memory")

__device__ __forceinline__ void ldm_x4(uint32_t* r, uint32_t a) {
    asm volatile("ldmatrix.sync.aligned.m8n8.x4.shared.b16 {%0,%1,%2,%3}, [%4];"
        : "=r"(r[0]), "=r"(r[1]), "=r"(r[2]), "=r"(r[3]) : "r"(a));
}
__device__ __forceinline__ void ldm_x2(uint32_t* r, uint32_t a) {
    asm volatile("ldmatrix.sync.aligned.m8n8.x2.shared.b16 {%0,%1}, [%2];"
        : "=r"(r[0]), "=r"(r[1]) : "r"(a));
}
#define MMA_BF16(acc, a, b) \
    asm volatile("mma.sync.aligned.m16n8k16.row.col.f32.bf16.bf16.f32 " \
        "{%0,%1,%2,%3}, {%4,%5,%6,%7}, {%8,%9}, {%0,%1,%2,%3};" \
        : "+f"((acc)[0]), "+f"((acc)[1]), "+f"((acc)[2]), "+f"((acc)[3]) \
        : "r"((a)[0]), "r"((a)[1]), "r"((a)[2]), "r"((a)[3]), "r"((b)[0]), "r"((b)[1]))

__device__ __forceinline__ void bsplit(float v, __nv_bfloat16& h, __nv_bfloat16& l)
{
    h = __float2bfloat16_rn(v);
    l = __float2bfloat16_rn(v - __bfloat162float(h));
}
__device__ __forceinline__ uint32_t rswz(int row) {   // 16B-group xor, 4 groups/row
    return (uint32_t)((((row >> 1) ^ (row >> 3)) & 3) << 4);
}

// ---------------- threefry2x32 / erfinv / rng ---------------------------------
__host__ __device__ __forceinline__ void threefry2x32(
    uint32_t ks0, uint32_t ks1, uint32_t x0, uint32_t x1,
    uint32_t& o0, uint32_t& o1)
{
    uint32_t ks2 = ks0 ^ ks1 ^ 0x1BD11BDAu;
    x0 += ks0; x1 += ks1;
#define TF_R(r) { x0 += x1; x1 = (x1 << (r)) | (x1 >> (32-(r))); x1 ^= x0; }
    TF_R(13) TF_R(15) TF_R(26) TF_R(6)   x0 += ks1; x1 += ks2 + 1u;
    TF_R(17) TF_R(29) TF_R(16) TF_R(24)  x0 += ks2; x1 += ks0 + 2u;
    TF_R(13) TF_R(15) TF_R(26) TF_R(6)   x0 += ks0; x1 += ks1 + 3u;
    TF_R(17) TF_R(29) TF_R(16) TF_R(24)  x0 += ks1; x1 += ks2 + 4u;
    TF_R(13) TF_R(15) TF_R(26) TF_R(6)   x0 += ks2; x1 += ks0 + 5u;
#undef TF_R
    o0 = x0; o1 = x1;
}

__device__ __forceinline__ float erfinv_xla(float x)
{
    float w = -log1pf(-x * x);
    float p;
    if (w < 5.0f) {
        w -= 2.5f;
        p = 2.81022636e-08f;
        p = fmaf(p, w, 3.43273939e-07f);
        p = fmaf(p, w, -3.5233877e-06f);
        p = fmaf(p, w, -4.39150654e-06f);
        p = fmaf(p, w, 0.00021858087f);
        p = fmaf(p, w, -0.00125372503f);
        p = fmaf(p, w, -0.00417768164f);
        p = fmaf(p, w, 0.246640727f);
        p = fmaf(p, w, 1.50140941f);
    } else {
        w = sqrtf(w) - 3.0f;
        p = -0.000200214257f;
        p = fmaf(p, w, 0.000100950558f);
        p = fmaf(p, w, 0.00134934322f);
        p = fmaf(p, w, -0.00367342844f);
        p = fmaf(p, w, 0.00573950773f);
        p = fmaf(p, w, -0.0076224613f);
        p = fmaf(p, w, 0.00943887047f);
        p = fmaf(p, w, 1.00167406f);
        p = fmaf(p, w, 2.83297682f);
    }
    return p * x;
}

__device__ __forceinline__ float rng_normal(uint32_t kx, uint32_t ky, uint32_t ctr)
{
    uint32_t a, b;
    threefry2x32(kx, ky, 0u, ctr, a, b);
    uint32_t bits = a ^ b;
    float f = __uint_as_float((bits >> 9) | 0x3F800000u) - 1.0f;
    const float lo = __uint_as_float(0xBF7FFFFFu);
    float u = fmaxf(lo, fmaf(f, 2.0f, lo));
    return 1.4142135623730951f * erfinv_xla(u);
}

// ---------------- mma.sync GEMM, 128x64 CTA tile, 4 warps, cp.async 2-stage ------
// D[128x64] tile of op(A[MxK]) @ B[NtotxK]^T  (3-term bf16 split emulation)
// EPI 0: Dout = D + bias (fp32)
// EPI 1: dual-tanh -> hf/hb bf16 splits (layer-1)
// EPI 2: fused update_f (ctl = D + bias)
// EPI 3: fused update_b
#define STG 24576      // stage bytes: AH 8K | AL 8K | BH 4K | BL 4K

template<int EPI>
__global__ __launch_bounds__(128)
void k_mma(const __nv_bfloat16* __restrict__ Ahi, const __nv_bfloat16* __restrict__ Alo,
           const __nv_bfloat16* __restrict__ Bhi, const __nv_bfloat16* __restrict__ Blo,
           int K, int Ntot,
           const float* __restrict__ bias, float* __restrict__ Dout,
           const float* __restrict__ Cadd, const float* __restrict__ wt,
           float tf, float tb,
           __nv_bfloat16* __restrict__ hf_hi, __nv_bfloat16* __restrict__ hf_lo,
           __nv_bfloat16* __restrict__ hb_hi, __nv_bfloat16* __restrict__ hb_lo,
           int t, const float* __restrict__ ss, const float* __restrict__ bsch,
           const float* __restrict__ mu_T, const float* __restrict__ sigma_T,
           float* __restrict__ chain, uint32_t kx, uint32_t ky)
{
    __shared__ __align__(16) char smem[2 * STG];
    const uint32_t sb = smem_u32(smem);
    const int tid = threadIdx.x, lane = tid & 31, wid = tid >> 5;
    const int bm = blockIdx.y * 128, bn = blockIdx.x * 64;
    const int wm = (wid & 1) * 64, wn = (wid >> 1) * 32;

    float acc[4][4][4];
#pragma unroll
    for (int mi = 0; mi < 4; mi++)
#pragma unroll
        for (int ni = 0; ni < 4; ni++)
#pragma unroll
            for (int r = 0; r < 4; r++) acc[mi][ni][r] = 0.f;

    const int NIT = K >> 5;

    // ---- async stage loader ----
    auto load_stage = [&](int st, int k0) {
        const uint32_t s0 = sb + st * STG;
#pragma unroll
        for (int v = 0; v < 4; v++) {
            int gi = tid + v * 128;                 // 0..511
            int row = gi >> 2, gc = gi & 3;
            uint32_t off = (uint32_t)(row * 64) + (((uint32_t)gc << 4) ^ rswz(row));
            const size_t go = (size_t)(bm + row) * K + k0 + gc * 8;
            cpa16(s0 + off,        Ahi + go);
            cpa16(s0 + 8192 + off, Alo + go);
        }
#pragma unroll
        for (int v = 0; v < 2; v++) {
            int gi = tid + v * 128;                 // 0..255
            int row = gi >> 2, gc = gi & 3;
            uint32_t off = (uint32_t)(row * 64) + (((uint32_t)gc << 4) ^ rswz(row));
            const size_t go = (size_t)(bn + row) * K + k0 + gc * 8;
            cpa16(s0 + 16384 + off, Bhi + go);
            cpa16(s0 + 20480 + off, Blo + go);
        }
        CPA_COMMIT();
    };

    load_stage(0, 0);
    if (NIT > 1) load_stage(1, 32);

    for (int it = 0; it < NIT; it++) {
        if (it + 1 < NIT) { CPA_WAIT1(); } else { CPA_WAIT0(); }
        __syncthreads();
        const uint32_t s0 = sb + (it & 1) * STG;
        const uint32_t sAH = s0, sAL = s0 + 8192, sBH = s0 + 16384, sBL = s0 + 20480;
#pragma unroll
        for (int ks = 0; ks < 2; ks++) {
            uint32_t ah[4][4], al[4][4], bh[4][2], bl[4][2];
#pragma unroll
            for (int mi = 0; mi < 4; mi++) {
                const int row = wm + mi * 16 + (lane & 15);
                const uint32_t cb = (uint32_t)((ks << 5) + ((lane >> 4) << 4));
                const uint32_t off = (uint32_t)(row * 64) + (cb ^ rswz(row));
                ldm_x4(ah[mi], sAH + off);
                ldm_x4(al[mi], sAL + off);
            }
#pragma unroll
            for (int ni = 0; ni < 4; ni++) {
                const int lm = lane & 15;
                const int n = wn + ni * 8 + (lm & 7);
                const uint32_t cb = (uint32_t)((ks << 5) + ((lm >> 3) << 4));
                const uint32_t off = (uint32_t)(n * 64) + (cb ^ rswz(n));
                ldm_x2(bh[ni], sBH + off);
                ldm_x2(bl[ni], sBL + off);
            }
#pragma unroll
            for (int mi = 0; mi < 4; mi++)
#pragma unroll
                for (int ni = 0; ni < 4; ni++) {
                    MMA_BF16(acc[mi][ni], ah[mi], bh[ni]);
                    MMA_BF16(acc[mi][ni], ah[mi], bl[ni]);
                    MMA_BF16(acc[mi][ni], al[mi], bh[ni]);
                }
        }
        __syncthreads();
        if (it + 2 < NIT) load_stage(it & 1, (it + 2) << 5);
    }

    // ---- epilogue ----
    const int er = lane >> 2;          // row within 8
    const int ec = (lane & 3) * 2;     // col pair base

    // scalar prefetch for update epilogues
    float sigU = 0.f, betaU = 0.f, s_U = 0.f, lsU = 0.f, sig2dt = 0.f;
    if (EPI == 2) {
        sigU = __ldg(&ss[t]); betaU = __ldg(&bsch[t]);
        s_U = sigU * SQRTDT_; lsU = logf(s_U); sig2dt = sigU * sigU * DT_;
    }
    if (EPI == 3) {
        const int tbi = (t + NSTEPS - 1) & (NSTEPS - 1);
        sigU = __ldg(&ss[tbi]); betaU = __ldg(&bsch[tbi]);
        s_U = sigU * SQRTDT_; lsU = logf(s_U); sig2dt = sigU * sigU * DT_;
    }

#pragma unroll
    for (int mi = 0; mi < 4; mi++) {
#pragma unroll
        for (int ni = 0; ni < 4; ni++) {
            const int row0 = bm + wm + mi * 16 + er;
            const int col = bn + wn + ni * 8 + ec;
            if (EPI == 0) {
                float2 bz = *(const float2*)(bias + col);
                *(float2*)(Dout + (size_t)row0 * Ntot + col) =
                    make_float2(acc[mi][ni][0] + bz.x, acc[mi][ni][1] + bz.y);
                *(float2*)(Dout + (size_t)(row0 + 8) * Ntot + col) =
                    make_float2(acc[mi][ni][2] + bz.x, acc[mi][ni][3] + bz.y);
            } else if (EPI == 1) {
                const float w0 = wt[col], w1 = wt[col + 1];
#pragma unroll
                for (int rr = 0; rr < 2; rr++) {
                    const size_t ro = (size_t)(row0 + rr * 8) * H_ + col;
                    float b0 = acc[mi][ni][rr * 2]     + Cadd[ro];
                    float b1 = acc[mi][ni][rr * 2 + 1] + Cadd[ro + 1];
                    float f0 = tanhf(fmaf(tf, w0, b0));
                    float f1 = tanhf(fmaf(tf, w1, b1));
                    float g0 = tanhf(fmaf(tb, w0, b0));
                    float g1 = tanhf(fmaf(tb, w1, b1));
                    __nv_bfloat16 h0, l0, h1, l1;
                    __nv_bfloat162 p;
                    bsplit(f0, h0, l0); bsplit(f1, h1, l1);
                    p.x = h0; p.y = h1; *(__nv_bfloat162*)(hf_hi + ro) = p;
                    p.x = l0; p.y = l1; *(__nv_bfloat162*)(hf_lo + ro) = p;
                    bsplit(g0, h0, l0); bsplit(g1, h1, l1);
                    p.x = h0; p.y = h1; *(__nv_bfloat162*)(hb_hi + ro) = p;
                    p.x = l0; p.y = l1; *(__nv_bfloat162*)(hb_lo + ro) = p;
                }
            } else {
                float2 bz = *(const float2*)(bias + col);
#pragma unroll
                for (int rr = 0; rr < 2; rr++) {
#pragma unroll
                    for (int cc = 0; cc < 2; cc++) {
                        const int row = row0 + rr * 8;
                        const int idx = row * ZD_ + col + cc;
                        float ctl = acc[mi][ni][rr * 2 + cc] + (cc ? bz.y : bz.x);
                        float m = mu_T[idx], st = sigma_T[idx];
                        float iv = 1.0f / (st * st);
                        if (EPI == 2) {
                            float z = g_z[idx];
                            float gg = (1.0f - betaU) * (-z) + betaU * (-(z - m) * iv);
                            float mu_f = z + fmaf(sig2dt, gg, ctl * DT_);
                            float e = rng_normal(kx, ky, (uint32_t)(t * SZ + idx));
                            float zn = fmaf(s_U, e, mu_f);
                            float d = (zn - mu_f) / s_U;
                            g_lw[idx] += 0.5f * d * d + lsU;
                            g_zn[idx] = zn;
                            chain[(size_t)(t + 1) * SZ + idx] = zn;
                            __nv_bfloat16 h, l; bsplit(zn, h, l);
                            g_zb_hi[idx] = h; g_zb_lo[idx] = l;
                        } else {  // EPI == 3
                            float zp = g_z[idx], zn = g_zn[idx];
                            float gg = (1.0f - betaU) * (-zn) + betaU * (-(zn - m) * iv);
                            float mu_b = zn + fmaf(sig2dt, gg, -ctl * DT_);
                            float d = (zp - mu_b) / s_U;
                            g_lw[idx] += -0.5f * d * d - lsU;
                            g_z[idx] = zn;
                        }
                    }
                }
            }
        }
    }
}

// ---------------- prep kernels --------------------------------------------------
__global__ void k_split_w(const float* __restrict__ src, int ld, int K, int total,
                          __nv_bfloat16* __restrict__ oh, __nv_bfloat16* __restrict__ ol)
{
    int idx = blockIdx.x * 256 + threadIdx.x;
    if (idx >= total) return;
    int n = idx / K, k = idx - n * K;
    float v = src[(size_t)k * ld + n];
    __nv_bfloat16 h, l; bsplit(v, h, l);
    oh[idx] = h; ol[idx] = l;
}

__global__ void k_split_plain(const float* __restrict__ src, int total,
                              __nv_bfloat16* __restrict__ oh, __nv_bfloat16* __restrict__ ol)
{
    int idx = blockIdx.x * 256 + threadIdx.x;
    if (idx >= total) return;
    __nv_bfloat16 h, l; bsplit(src[idx], h, l);
    oh[idx] = h; ol[idx] = l;
}

__global__ void k_init(float* __restrict__ chain, uint32_t kx, uint32_t ky)
{
    int idx = blockIdx.x * 256 + threadIdx.x;
    if (idx >= SZ) return;
    float z0 = rng_normal(kx, ky, (uint32_t)idx);
    g_z[idx] = z0;
    chain[idx] = z0;
    g_lw[idx] = 0.f;
    __nv_bfloat16 h, l; bsplit(z0, h, l);
    g_zb_hi[idx] = h; g_zb_lo[idx] = l;
}

__global__ void k_final(const float* __restrict__ mu_T, const float* __restrict__ sigma_T,
                        const float* __restrict__ chain)
{
    __shared__ double sd[256];
    int gid = blockIdx.x * 256 + threadIdx.x;
    double s = 0.0;
#pragma unroll
    for (int r = 0; r < 4; r++) {
        int idx = r * (SZ / 4) + gid;
        float zT = g_z[idx];
        float z0 = chain[idx];
        float m = mu_T[idx], st = sigma_T[idx];
        float dd = (zT - m) / st;
        float lw = g_lw[idx] + (-0.5f * dd * dd - logf(st) + 0.5f * z0 * z0);
        s += (double)lw;
    }
    sd[threadIdx.x] = s;
    __syncthreads();
    for (int o = 128; o > 0; o >>= 1) {
        if (threadIdx.x < o) sd[threadIdx.x] += sd[threadIdx.x + o];
        __syncthreads();
    }
    if (threadIdx.x == 0) g_part[blockIdx.x] = sd[0];
}

__global__ void k_reduce(float* __restrict__ out)
{
    __shared__ double sd[256];
    double s = 0.0;
    for (int i = threadIdx.x; i < 2048; i += 256) s += g_part[i];
    sd[threadIdx.x] = s;
    __syncthreads();
    for (int o = 128; o > 0; o >>= 1) {
        if (threadIdx.x < o) sd[threadIdx.x] += sd[threadIdx.x + o];
        __syncthreads();
    }
    if (threadIdx.x == 0) out[0] = (float)(sd[0] / (double)B_);
}

// ---------------- launch ------------------------------------------------------
extern "C" void kernel_launch(void* const* d_in, const int* in_sizes, int n_in,
                              void* d_out, int out_size)
{
    (void)in_sizes; (void)n_in; (void)out_size;
    const float* ctx     = (const float*)d_in[0];
    const float* mu_T    = (const float*)d_in[1];
    const float* sigma_T = (const float*)d_in[2];
    const float* W1      = (const float*)d_in[3];   // (513, 512)
    const float* b1      = (const float*)d_in[4];
    const float* W2      = (const float*)d_in[5];   // (512, 256)
    const float* b2      = (const float*)d_in[6];
    const float* ss      = (const float*)d_in[7];
    const float* bsch    = (const float*)d_in[8];
    float* out   = (float*)d_out;
    float* chain = out + 1;
    const float* w1t = W1 + 512 * H_;               // t-coefficient row

    uint32_t k0x, k0y, k1x, k1y;
    threefry2x32(0u, 42u, 0u, 0u, k0x, k0y);
    threefry2x32(0u, 42u, 0u, 1u, k1x, k1y);

    struct Ptrs {
        float *C;
        __nv_bfloat16 *zb_h, *zb_l, *cx_h, *cx_l, *hf_h, *hf_l, *hb_h, *hb_l;
        __nv_bfloat16 *w1z_h, *w1z_l, *w1c_h, *w1c_l, *w2_h, *w2_l;
        bool init;
    };
    static Ptrs P = {};
    if (!P.init) {
        cudaGetSymbolAddress((void**)&P.C, g_C);
        cudaGetSymbolAddress((void**)&P.zb_h, g_zb_hi);  cudaGetSymbolAddress((void**)&P.zb_l, g_zb_lo);
        cudaGetSymbolAddress((void**)&P.cx_h, g_ctxb_hi); cudaGetSymbolAddress((void**)&P.cx_l, g_ctxb_lo);
        cudaGetSymbolAddress((void**)&P.hf_h, g_hf_hi);  cudaGetSymbolAddress((void**)&P.hf_l, g_hf_lo);
        cudaGetSymbolAddress((void**)&P.hb_h, g_hb_hi);  cudaGetSymbolAddress((void**)&P.hb_l, g_hb_lo);
        cudaGetSymbolAddress((void**)&P.w1z_h, g_w1zt_hi); cudaGetSymbolAddress((void**)&P.w1z_l, g_w1zt_lo);
        cudaGetSymbolAddress((void**)&P.w1c_h, g_w1ct_hi); cudaGetSymbolAddress((void**)&P.w1c_l, g_w1ct_lo);
        cudaGetSymbolAddress((void**)&P.w2_h, g_w2t_hi);   cudaGetSymbolAddress((void**)&P.w2_l, g_w2t_lo);
        P.init = true;
    }

    const int EB = SZ / 256;
    const dim3 gL1(H_ / 64, B_ / 128);     // (8,64) = 512 blocks, layer-1 / C
    const dim3 gCT(ZD_ / 64, B_ / 128);    // (4,64) = 256 blocks, ctl GEMMs

    // ---- prologue ----
    k_split_w<<<(H_ * ZD_ + 255) / 256, 256>>>(W1,            H_, ZD_, H_ * ZD_, P.w1z_h, P.w1z_l);
    k_split_w<<<(H_ * CD_ + 255) / 256, 256>>>(W1 + 256 * H_, H_, CD_, H_ * CD_, P.w1c_h, P.w1c_l);
    k_split_w<<<(ZD_ * H_ + 255) / 256, 256>>>(W2,           ZD_, H_, ZD_ * H_,  P.w2_h,  P.w2_l);
    k_split_plain<<<EB, 256>>>(ctx, SZ, P.cx_h, P.cx_l);
    k_init<<<EB, 256>>>(chain, k0x, k0y);

    // C = ctx @ W1_ctx + b1
    k_mma<0><<<gL1, 128>>>(P.cx_h, P.cx_l, P.w1c_h, P.w1c_l, CD_, H_,
                           b1, P.C, nullptr, nullptr, 0.f, 0.f,
                           nullptr, nullptr, nullptr, nullptr,
                           0, nullptr, nullptr, nullptr, nullptr, nullptr, 0u, 0u);
    // layer-1 on z0: hf_0 (tf=1/32); hb slot written but unused this step
    k_mma<1><<<gL1, 128>>>(P.zb_h, P.zb_l, P.w1z_h, P.w1z_l, ZD_, H_,
                           nullptr, nullptr, P.C, w1t, 1.0f / NSTEPS, -1.0f / NSTEPS,
                           P.hf_h, P.hf_l, P.hb_h, P.hb_l,
                           0, nullptr, nullptr, nullptr, nullptr, nullptr, 0u, 0u);

    for (int t = 0; t < NSTEPS; t++) {
        // ctl_f = hf @ W2 + b2, fused forward update
        k_mma<2><<<gCT, 128>>>(P.hf_h, P.hf_l, P.w2_h, P.w2_l, H_, ZD_,
                               b2, nullptr, nullptr, nullptr, 0.f, 0.f,
                               nullptr, nullptr, nullptr, nullptr,
                               t, ss, bsch, mu_T, sigma_T, chain, k1x, k1y);
        // layer-1 on z_{t+1}: hf_{t+1} (tf=(t+2)/32), hb_t (tb=t/32)
        k_mma<1><<<gL1, 128>>>(P.zb_h, P.zb_l, P.w1z_h, P.w1z_l, ZD_, H_,
                               nullptr, nullptr, P.C, w1t,
                               (float)(t + 2) / NSTEPS, (float)t / NSTEPS,
                               P.hf_h, P.hf_l, P.hb_h, P.hb_l,
                               0, nullptr, nullptr, nullptr, nullptr, nullptr, 0u, 0u);
        // ctl_b = hb @ W2 + b2, fused backward update
        k_mma<3><<<gCT, 128>>>(P.hb_h, P.hb_l, P.w2_h, P.w2_l, H_, ZD_,
                               b2, nullptr, nullptr, nullptr, 0.f, 0.f,
                               nullptr, nullptr, nullptr, nullptr,
                               t, ss, bsch, mu_T, sigma_T, chain, k1x, k1y);
    }

    k_final<<<2048, 256>>>(mu_T, sigma_T, chain);
    k_reduce<<<1, 256>>>(out);
}